// round 1
// baseline (speedup 1.0000x reference)
#include <cuda_runtime.h>
#include <cstdint>
#include <cstddef>

// ---------------------------------------------------------------------------
// CustomCrossAttention: out = softmax((xWq)(yWk)^T/sqrt(D) + bias) (yWv) Wo^T
// B=2, SQ=SKV=2048, EMBED=1024, NHEAD=16, HEAD_DIM=64, fp32 I/O.
// Strategy: TF32 mma.sync for all GEMMs + flash attention. Scratch in
// __device__ globals (no allocation; graph-capturable).
// ---------------------------------------------------------------------------

#define EMBED   1024
#define NHEAD   16
#define HDIM    64
#define BATCH   2
#define SQLEN   2048
#define SKVLEN  2048
#define MTOT    (BATCH * SQLEN)   // 4096 rows for all projections

// 64 MB of scratch: q,k,v projections + attention output
__device__ float g_q[MTOT * EMBED];
__device__ float g_k[MTOT * EMBED];
__device__ float g_v[MTOT * EMBED];
__device__ float g_attn[MTOT * EMBED];

// ---------------------------------------------------------------------------
// TF32 helpers
// ---------------------------------------------------------------------------
__device__ __forceinline__ float f2tf32(float x) {
    uint32_t r;
    asm("cvt.rna.tf32.f32 %0, %1;" : "=r"(r) : "f"(x));
    return __uint_as_float(r);
}

__device__ __forceinline__ void mma_tf32(float c[4],
                                         uint32_t a0, uint32_t a1, uint32_t a2, uint32_t a3,
                                         uint32_t b0, uint32_t b1) {
    asm volatile(
        "mma.sync.aligned.m16n8k8.row.col.f32.tf32.tf32.f32 "
        "{%0,%1,%2,%3}, {%4,%5,%6,%7}, {%8,%9}, {%0,%1,%2,%3};"
        : "+f"(c[0]), "+f"(c[1]), "+f"(c[2]), "+f"(c[3])
        : "r"(a0), "r"(a1), "r"(a2), "r"(a3), "r"(b0), "r"(b1));
}

// ---------------------------------------------------------------------------
// GEMM: C[M,N] = A[M,K] @ W[N,K]^T   (all row-major fp32, TF32 compute)
// Block tile 128x128, K-tile 32. 256 threads = 8 warps (2x4), warp tile 64x32.
// ---------------------------------------------------------------------------
#define GBM 128
#define GBN 128
#define GBK 32
#define GPAD 36   // smem row stride (floats); (4g+tg) mod 32 covers all banks

__global__ __launch_bounds__(256) void gemm_xwt(const float* __restrict__ A,
                                                const float* __restrict__ W,
                                                float* __restrict__ C,
                                                int M, int N, int K) {
    __shared__ float As[GBM][GPAD];
    __shared__ float Bs[GBN][GPAD];

    const int tid  = threadIdx.x;
    const int bm   = blockIdx.y;
    const int bn   = blockIdx.x;
    const int wid  = tid >> 5;
    const int lane = tid & 31;
    const int g    = lane >> 2;   // 0..7
    const int tg   = lane & 3;    // 0..3
    const int wm   = wid >> 2;    // 0..1 -> 64 rows
    const int wn   = wid & 3;     // 0..3 -> 32 cols

    float acc[4][4][4];
#pragma unroll
    for (int i = 0; i < 4; i++)
#pragma unroll
        for (int j = 0; j < 4; j++)
#pragma unroll
            for (int r = 0; r < 4; r++) acc[i][j][r] = 0.f;

    const int lrow = tid >> 3;        // 0..31
    const int lcol = (tid & 7) * 4;   // 0..28 step 4

    for (int kt = 0; kt < K; kt += GBK) {
        // Load 128x32 A tile and 128x32 W tile (as [n][k]), TF32-rounded.
#pragma unroll
        for (int p = 0; p < 4; p++) {
            int r = lrow + p * 32;
            float4 av = *reinterpret_cast<const float4*>(
                &A[(size_t)(bm * GBM + r) * K + kt + lcol]);
            As[r][lcol + 0] = f2tf32(av.x);
            As[r][lcol + 1] = f2tf32(av.y);
            As[r][lcol + 2] = f2tf32(av.z);
            As[r][lcol + 3] = f2tf32(av.w);
            float4 bv = *reinterpret_cast<const float4*>(
                &W[(size_t)(bn * GBN + r) * K + kt + lcol]);
            Bs[r][lcol + 0] = f2tf32(bv.x);
            Bs[r][lcol + 1] = f2tf32(bv.y);
            Bs[r][lcol + 2] = f2tf32(bv.z);
            Bs[r][lcol + 3] = f2tf32(bv.w);
        }
        __syncthreads();

#pragma unroll
        for (int ks = 0; ks < 4; ks++) {
            uint32_t af[4][4];
#pragma unroll
            for (int mt = 0; mt < 4; mt++) {
                int rb = wm * 64 + mt * 16;
                af[mt][0] = __float_as_uint(As[rb + g][ks * 8 + tg]);
                af[mt][1] = __float_as_uint(As[rb + g + 8][ks * 8 + tg]);
                af[mt][2] = __float_as_uint(As[rb + g][ks * 8 + tg + 4]);
                af[mt][3] = __float_as_uint(As[rb + g + 8][ks * 8 + tg + 4]);
            }
#pragma unroll
            for (int nt = 0; nt < 4; nt++) {
                int cb = wn * 32 + nt * 8;
                uint32_t b0 = __float_as_uint(Bs[cb + g][ks * 8 + tg]);
                uint32_t b1 = __float_as_uint(Bs[cb + g][ks * 8 + tg + 4]);
#pragma unroll
                for (int mt = 0; mt < 4; mt++)
                    mma_tf32(acc[mt][nt], af[mt][0], af[mt][1], af[mt][2], af[mt][3], b0, b1);
            }
        }
        __syncthreads();
    }

    // Epilogue: direct stores (C fragment layout)
#pragma unroll
    for (int mt = 0; mt < 4; mt++) {
        int r0 = bm * GBM + wm * 64 + mt * 16 + g;
#pragma unroll
        for (int nt = 0; nt < 4; nt++) {
            int c0 = bn * GBN + wn * 32 + nt * 8 + 2 * tg;
            C[(size_t)r0 * N + c0]           = acc[mt][nt][0];
            C[(size_t)r0 * N + c0 + 1]       = acc[mt][nt][1];
            C[(size_t)(r0 + 8) * N + c0]     = acc[mt][nt][2];
            C[(size_t)(r0 + 8) * N + c0 + 1] = acc[mt][nt][3];
        }
    }
}

// ---------------------------------------------------------------------------
// Flash attention: per block one (b, h, 64-row Q tile). 128 threads = 4 warps,
// each warp owns 16 Q rows. KV consumed in 64-row tiles with online softmax.
// bias[b, kv] is added to scores before softmax (broadcast over heads/queries).
// ---------------------------------------------------------------------------
#define APAD 68   // smem row stride for 64-wide tiles

__global__ __launch_bounds__(128) void attn_kernel(const float* __restrict__ bias) {
    extern __shared__ float smem[];
    float* Qs = smem;                 // [64][APAD]
    float* Ks = smem + 64 * APAD;     // [64][APAD]
    float* Vs = smem + 2 * 64 * APAD; // [64][APAD]
    float* Ps = smem + 3 * 64 * APAD; // [64][APAD]

    const int tid  = threadIdx.x;
    const int warp = tid >> 5;
    const int lane = tid & 31;
    const int g    = lane >> 2;
    const int tg   = lane & 3;
    const int qt   = blockIdx.x;   // 0..31
    const int h    = blockIdx.y;   // 0..15
    const int b    = blockIdx.z;   // 0..1

    const int lr = tid >> 4;         // 0..7
    const int lc = (tid & 15) * 4;   // 0..60 step 4

    // Load 64x64 Q tile (TF32-rounded)
    const float* Qg = g_q + (size_t)(b * SQLEN + qt * 64) * EMBED + h * HDIM;
#pragma unroll
    for (int p = 0; p < 8; p++) {
        int r = lr + p * 8;
        float4 v = *reinterpret_cast<const float4*>(&Qg[(size_t)r * EMBED + lc]);
        Qs[r * APAD + lc + 0] = f2tf32(v.x);
        Qs[r * APAD + lc + 1] = f2tf32(v.y);
        Qs[r * APAD + lc + 2] = f2tf32(v.z);
        Qs[r * APAD + lc + 3] = f2tf32(v.w);
    }
    __syncthreads();

    float m_st[2] = {-1e30f, -1e30f};
    float l_st[2] = {0.f, 0.f};
    float o[8][4];
#pragma unroll
    for (int dt = 0; dt < 8; dt++)
#pragma unroll
        for (int r = 0; r < 4; r++) o[dt][r] = 0.f;

    for (int kv0 = 0; kv0 < SKVLEN; kv0 += 64) {
        // Load K,V tiles (TF32-rounded)
        const float* Kg = g_k + (size_t)(b * SKVLEN + kv0) * EMBED + h * HDIM;
        const float* Vg = g_v + (size_t)(b * SKVLEN + kv0) * EMBED + h * HDIM;
#pragma unroll
        for (int p = 0; p < 8; p++) {
            int r = lr + p * 8;
            float4 kvv = *reinterpret_cast<const float4*>(&Kg[(size_t)r * EMBED + lc]);
            Ks[r * APAD + lc + 0] = f2tf32(kvv.x);
            Ks[r * APAD + lc + 1] = f2tf32(kvv.y);
            Ks[r * APAD + lc + 2] = f2tf32(kvv.z);
            Ks[r * APAD + lc + 3] = f2tf32(kvv.w);
            float4 vv = *reinterpret_cast<const float4*>(&Vg[(size_t)r * EMBED + lc]);
            Vs[r * APAD + lc + 0] = f2tf32(vv.x);
            Vs[r * APAD + lc + 1] = f2tf32(vv.y);
            Vs[r * APAD + lc + 2] = f2tf32(vv.z);
            Vs[r * APAD + lc + 3] = f2tf32(vv.w);
        }
        __syncthreads();

        // S = Q @ K^T : 16 q rows x 64 kv cols per warp
        float s[8][4];
#pragma unroll
        for (int nt = 0; nt < 8; nt++)
#pragma unroll
            for (int r = 0; r < 4; r++) s[nt][r] = 0.f;

        const int rb = warp * 16;
#pragma unroll
        for (int ks = 0; ks < 8; ks++) {
            uint32_t a0 = __float_as_uint(Qs[(rb + g) * APAD + ks * 8 + tg]);
            uint32_t a1 = __float_as_uint(Qs[(rb + g + 8) * APAD + ks * 8 + tg]);
            uint32_t a2 = __float_as_uint(Qs[(rb + g) * APAD + ks * 8 + tg + 4]);
            uint32_t a3 = __float_as_uint(Qs[(rb + g + 8) * APAD + ks * 8 + tg + 4]);
#pragma unroll
            for (int nt = 0; nt < 8; nt++) {
                uint32_t b0 = __float_as_uint(Ks[(nt * 8 + g) * APAD + ks * 8 + tg]);
                uint32_t b1 = __float_as_uint(Ks[(nt * 8 + g) * APAD + ks * 8 + tg + 4]);
                mma_tf32(s[nt], a0, a1, a2, a3, b0, b1);
            }
        }

        // scale + bias, online softmax
        float mnew[2] = {m_st[0], m_st[1]};
#pragma unroll
        for (int nt = 0; nt < 8; nt++) {
            int c = kv0 + nt * 8 + 2 * tg;
            float b0v = __ldg(&bias[(size_t)b * SKVLEN + c]);
            float b1v = __ldg(&bias[(size_t)b * SKVLEN + c + 1]);
            s[nt][0] = s[nt][0] * 0.125f + b0v;
            s[nt][1] = s[nt][1] * 0.125f + b1v;
            s[nt][2] = s[nt][2] * 0.125f + b0v;
            s[nt][3] = s[nt][3] * 0.125f + b1v;
            mnew[0] = fmaxf(mnew[0], fmaxf(s[nt][0], s[nt][1]));
            mnew[1] = fmaxf(mnew[1], fmaxf(s[nt][2], s[nt][3]));
        }
        // reduce max across the quad (threads sharing the same rows)
#pragma unroll
        for (int r = 0; r < 2; r++) {
            mnew[r] = fmaxf(mnew[r], __shfl_xor_sync(0xffffffffu, mnew[r], 1));
            mnew[r] = fmaxf(mnew[r], __shfl_xor_sync(0xffffffffu, mnew[r], 2));
        }

        float alpha0 = __expf(m_st[0] - mnew[0]);
        float alpha1 = __expf(m_st[1] - mnew[1]);

        float rowsum[2] = {0.f, 0.f};
#pragma unroll
        for (int nt = 0; nt < 8; nt++) {
            s[nt][0] = __expf(s[nt][0] - mnew[0]);
            s[nt][1] = __expf(s[nt][1] - mnew[0]);
            s[nt][2] = __expf(s[nt][2] - mnew[1]);
            s[nt][3] = __expf(s[nt][3] - mnew[1]);
            rowsum[0] += s[nt][0] + s[nt][1];
            rowsum[1] += s[nt][2] + s[nt][3];
        }
#pragma unroll
        for (int r = 0; r < 2; r++) {
            rowsum[r] += __shfl_xor_sync(0xffffffffu, rowsum[r], 1);
            rowsum[r] += __shfl_xor_sync(0xffffffffu, rowsum[r], 2);
        }
        l_st[0] = l_st[0] * alpha0 + rowsum[0];
        l_st[1] = l_st[1] * alpha1 + rowsum[1];
        m_st[0] = mnew[0];
        m_st[1] = mnew[1];

        // rescale running O
#pragma unroll
        for (int dt = 0; dt < 8; dt++) {
            o[dt][0] *= alpha0;
            o[dt][1] *= alpha0;
            o[dt][2] *= alpha1;
            o[dt][3] *= alpha1;
        }

        // stage P into this warp's private smem rows (A-fragment source)
#pragma unroll
        for (int nt = 0; nt < 8; nt++) {
            Ps[(rb + g) * APAD + nt * 8 + 2 * tg]         = f2tf32(s[nt][0]);
            Ps[(rb + g) * APAD + nt * 8 + 2 * tg + 1]     = f2tf32(s[nt][1]);
            Ps[(rb + g + 8) * APAD + nt * 8 + 2 * tg]     = f2tf32(s[nt][2]);
            Ps[(rb + g + 8) * APAD + nt * 8 + 2 * tg + 1] = f2tf32(s[nt][3]);
        }
        __syncwarp();

        // O += P @ V
#pragma unroll
        for (int ks = 0; ks < 8; ks++) {
            uint32_t a0 = __float_as_uint(Ps[(rb + g) * APAD + ks * 8 + tg]);
            uint32_t a1 = __float_as_uint(Ps[(rb + g + 8) * APAD + ks * 8 + tg]);
            uint32_t a2 = __float_as_uint(Ps[(rb + g) * APAD + ks * 8 + tg + 4]);
            uint32_t a3 = __float_as_uint(Ps[(rb + g + 8) * APAD + ks * 8 + tg + 4]);
#pragma unroll
            for (int dt = 0; dt < 8; dt++) {
                uint32_t b0 = __float_as_uint(Vs[(ks * 8 + tg) * APAD + dt * 8 + g]);
                uint32_t b1 = __float_as_uint(Vs[(ks * 8 + tg + 4) * APAD + dt * 8 + g]);
                mma_tf32(o[dt], a0, a1, a2, a3, b0, b1);
            }
        }
        __syncthreads();   // Ks/Vs consumed by all warps before next tile load
    }

    // Epilogue: O / l -> g_attn[b, q, h*64 + d]
    float inv0 = 1.f / l_st[0];
    float inv1 = 1.f / l_st[1];
    const int q0 = qt * 64 + warp * 16 + g;
    float* Og = g_attn + (size_t)(b * SQLEN) * EMBED + h * HDIM;
#pragma unroll
    for (int dt = 0; dt < 8; dt++) {
        int c = dt * 8 + 2 * tg;
        Og[(size_t)q0 * EMBED + c]           = o[dt][0] * inv0;
        Og[(size_t)q0 * EMBED + c + 1]       = o[dt][1] * inv0;
        Og[(size_t)(q0 + 8) * EMBED + c]     = o[dt][2] * inv1;
        Og[(size_t)(q0 + 8) * EMBED + c + 1] = o[dt][3] * inv1;
    }
}

// ---------------------------------------------------------------------------
// Launch
// ---------------------------------------------------------------------------
extern "C" void kernel_launch(void* const* d_in, const int* in_sizes, int n_in,
                              void* d_out, int out_size) {
    const float* query = (const float*)d_in[0];
    const float* key   = (const float*)d_in[1];
    const float* value = (const float*)d_in[2];
    const float* bias  = (const float*)d_in[3];
    const float* Wq    = (const float*)d_in[4];
    const float* Wk    = (const float*)d_in[5];
    const float* Wv    = (const float*)d_in[6];
    const float* Wo    = (const float*)d_in[7];
    float* out = (float*)d_out;

    float *gq, *gk, *gv, *ga;
    cudaGetSymbolAddress((void**)&gq, g_q);
    cudaGetSymbolAddress((void**)&gk, g_k);
    cudaGetSymbolAddress((void**)&gv, g_v);
    cudaGetSymbolAddress((void**)&ga, g_attn);

    const int attn_smem = 4 * 64 * APAD * (int)sizeof(float);  // 69632 B
    cudaFuncSetAttribute(attn_kernel, cudaFuncAttributeMaxDynamicSharedMemorySize,
                         attn_smem);

    dim3 gemm_grid(EMBED / GBN, MTOT / GBM);  // (8, 32)

    gemm_xwt<<<gemm_grid, 256>>>(query, Wq, gq, MTOT, EMBED, EMBED);
    gemm_xwt<<<gemm_grid, 256>>>(key,   Wk, gk, MTOT, EMBED, EMBED);
    gemm_xwt<<<gemm_grid, 256>>>(value, Wv, gv, MTOT, EMBED, EMBED);

    dim3 attn_grid(SQLEN / 64, NHEAD, BATCH);  // (32, 16, 2)
    attn_kernel<<<attn_grid, 128, attn_smem>>>(bias);

    gemm_xwt<<<gemm_grid, 256>>>(ga, Wo, out, MTOT, EMBED, EMBED);
}

// round 2
// speedup vs baseline: 1.4161x; 1.4161x over previous
#include <cuda_runtime.h>
#include <cstdint>
#include <cstddef>

// ---------------------------------------------------------------------------
// CustomCrossAttention: out = softmax((xWq)(yWk)^T/8 + bias) (yWv) Wo^T
// B=2, SQ=SKV=2048, EMBED=1024, NHEAD=16, HEAD_DIM=64, fp32 I/O, TF32 mma.
// R2: attn warp-M 32 rows, shuffle-based S->P fragment conversion (no Ps smem),
//     conflict-free V pad, 4 CTAs/SM single-wave grid; GEMMs get register
//     double-buffering + merged QKV launch.
// ---------------------------------------------------------------------------

#define EMBED   1024
#define NHEAD   16
#define HDIM    64
#define BATCH   2
#define SQLEN   2048
#define SKVLEN  2048
#define MTOT    (BATCH * SQLEN)

__device__ float g_q[MTOT * EMBED];
__device__ float g_k[MTOT * EMBED];
__device__ float g_v[MTOT * EMBED];
__device__ float g_attn[MTOT * EMBED];

__device__ __forceinline__ float f2tf32(float x) {
    uint32_t r;
    asm("cvt.rna.tf32.f32 %0, %1;" : "=r"(r) : "f"(x));
    return __uint_as_float(r);
}

__device__ __forceinline__ void mma_tf32(float c[4],
                                         uint32_t a0, uint32_t a1, uint32_t a2, uint32_t a3,
                                         uint32_t b0, uint32_t b1) {
    asm volatile(
        "mma.sync.aligned.m16n8k8.row.col.f32.tf32.tf32.f32 "
        "{%0,%1,%2,%3}, {%4,%5,%6,%7}, {%8,%9}, {%0,%1,%2,%3};"
        : "+f"(c[0]), "+f"(c[1]), "+f"(c[2]), "+f"(c[3])
        : "r"(a0), "r"(a1), "r"(a2), "r"(a3), "r"(b0), "r"(b1));
}

// ---------------------------------------------------------------------------
// GEMM: C[M,N] = A[M,K] @ W[N,K]^T, 128x128x32 tile, 256 thr, reg double-buffer
// ---------------------------------------------------------------------------
#define GBM 128
#define GBN 128
#define GBK 32
#define GPAD 36

__device__ __forceinline__ void gemm_body(const float* __restrict__ A,
                                          const float* __restrict__ W,
                                          float* __restrict__ C,
                                          int bm, int bn) {
    __shared__ float As[GBM][GPAD];
    __shared__ float Bs[GBN][GPAD];
    const int K = EMBED, N = EMBED;

    const int tid  = threadIdx.x;
    const int wid  = tid >> 5;
    const int lane = tid & 31;
    const int g    = lane >> 2;
    const int tg   = lane & 3;
    const int wm   = wid >> 2;
    const int wn   = wid & 3;

    float acc[4][4][4];
#pragma unroll
    for (int i = 0; i < 4; i++)
#pragma unroll
        for (int j = 0; j < 4; j++)
#pragma unroll
            for (int r = 0; r < 4; r++) acc[i][j][r] = 0.f;

    const int lrow = tid >> 3;
    const int lc   = (tid & 7) * 4;
    const float* Ab = A + (size_t)(bm * GBM) * K;
    const float* Wb = W + (size_t)(bn * GBN) * K;

    float4 ra[4], rb[4];
#pragma unroll
    for (int p = 0; p < 4; p++) {
        ra[p] = *reinterpret_cast<const float4*>(&Ab[(size_t)(lrow + p * 32) * K + lc]);
        rb[p] = *reinterpret_cast<const float4*>(&Wb[(size_t)(lrow + p * 32) * K + lc]);
    }

    const int niter = K / GBK;
    for (int it = 0; it < niter; it++) {
#pragma unroll
        for (int p = 0; p < 4; p++) {
            float4 ta, tb;
            ta.x = f2tf32(ra[p].x); ta.y = f2tf32(ra[p].y);
            ta.z = f2tf32(ra[p].z); ta.w = f2tf32(ra[p].w);
            tb.x = f2tf32(rb[p].x); tb.y = f2tf32(rb[p].y);
            tb.z = f2tf32(rb[p].z); tb.w = f2tf32(rb[p].w);
            *reinterpret_cast<float4*>(&As[lrow + p * 32][lc]) = ta;
            *reinterpret_cast<float4*>(&Bs[lrow + p * 32][lc]) = tb;
        }
        __syncthreads();

        if (it + 1 < niter) {
            const int ko = (it + 1) * GBK;
#pragma unroll
            for (int p = 0; p < 4; p++) {
                ra[p] = *reinterpret_cast<const float4*>(&Ab[(size_t)(lrow + p * 32) * K + ko + lc]);
                rb[p] = *reinterpret_cast<const float4*>(&Wb[(size_t)(lrow + p * 32) * K + ko + lc]);
            }
        }

#pragma unroll
        for (int ks = 0; ks < 4; ks++) {
            uint32_t af[4][4];
#pragma unroll
            for (int mt = 0; mt < 4; mt++) {
                int rbse = wm * 64 + mt * 16;
                af[mt][0] = __float_as_uint(As[rbse + g][ks * 8 + tg]);
                af[mt][1] = __float_as_uint(As[rbse + g + 8][ks * 8 + tg]);
                af[mt][2] = __float_as_uint(As[rbse + g][ks * 8 + tg + 4]);
                af[mt][3] = __float_as_uint(As[rbse + g + 8][ks * 8 + tg + 4]);
            }
#pragma unroll
            for (int nt = 0; nt < 4; nt++) {
                int cb = wn * 32 + nt * 8;
                uint32_t b0 = __float_as_uint(Bs[cb + g][ks * 8 + tg]);
                uint32_t b1 = __float_as_uint(Bs[cb + g][ks * 8 + tg + 4]);
#pragma unroll
                for (int mt = 0; mt < 4; mt++)
                    mma_tf32(acc[mt][nt], af[mt][0], af[mt][1], af[mt][2], af[mt][3], b0, b1);
            }
        }
        __syncthreads();
    }

#pragma unroll
    for (int mt = 0; mt < 4; mt++) {
        int r0 = bm * GBM + wm * 64 + mt * 16 + g;
#pragma unroll
        for (int nt = 0; nt < 4; nt++) {
            int c0 = bn * GBN + wn * 32 + nt * 8 + 2 * tg;
            float2 lo = {acc[mt][nt][0], acc[mt][nt][1]};
            float2 hi = {acc[mt][nt][2], acc[mt][nt][3]};
            *reinterpret_cast<float2*>(&C[(size_t)r0 * N + c0])       = lo;
            *reinterpret_cast<float2*>(&C[(size_t)(r0 + 8) * N + c0]) = hi;
        }
    }
}

__global__ __launch_bounds__(256, 2) void gemm_single(const float* __restrict__ A,
                                                      const float* __restrict__ W,
                                                      float* __restrict__ C) {
    gemm_body(A, W, C, blockIdx.y, blockIdx.x);
}

__global__ __launch_bounds__(256, 2) void gemm_qkv(const float* __restrict__ q,
                                                   const float* __restrict__ k,
                                                   const float* __restrict__ v,
                                                   const float* __restrict__ Wq,
                                                   const float* __restrict__ Wk,
                                                   const float* __restrict__ Wv,
                                                   float* __restrict__ oq,
                                                   float* __restrict__ ok,
                                                   float* __restrict__ ov) {
    const int z = blockIdx.z;
    const float* A = (z == 0) ? q : (z == 1) ? k : v;
    const float* W = (z == 0) ? Wq : (z == 1) ? Wk : Wv;
    float* C       = (z == 0) ? oq : (z == 1) ? ok : ov;
    gemm_body(A, W, C, blockIdx.y, blockIdx.x);
}

// ---------------------------------------------------------------------------
// Flash attention v2: block = 128 Q rows, 4 warps (32 rows each), KV tile = 32.
// S->P fragment conversion via quad shuffles (no P smem). 4 CTAs/SM.
// ---------------------------------------------------------------------------
#define QPAD 68
#define KPAD 68
#define VPAD 72
#define KVT  32
#define ATTN_SMEM ((128 * QPAD + KVT * KPAD + KVT * VPAD) * 4)

__global__ __launch_bounds__(128, 4) void attn_kernel(const float* __restrict__ bias) {
    extern __shared__ float sm[];
    float* Qs = sm;                           // [128][QPAD]
    float* Ks = sm + 128 * QPAD;              // [KVT][KPAD]
    float* Vs = sm + 128 * QPAD + KVT * KPAD; // [KVT][VPAD]

    const int tid  = threadIdx.x;
    const int warp = tid >> 5;
    const int lane = tid & 31;
    const int g    = lane >> 2;
    const int tg   = lane & 3;
    const int qt   = blockIdx.x;   // 0..15 (128-row tiles)
    const int h    = blockIdx.y;
    const int b    = blockIdx.z;

    const int lr = tid >> 4;         // 0..7
    const int lc = (tid & 15) * 4;   // 0..60 step 4

    // Load 128x64 Q tile (TF32-rounded)
    const float* Qg = g_q + (size_t)(b * SQLEN + qt * 128) * EMBED + h * HDIM;
#pragma unroll
    for (int p = 0; p < 16; p++) {
        int r = lr + p * 8;
        float4 v = *reinterpret_cast<const float4*>(&Qg[(size_t)r * EMBED + lc]);
        float4 t;
        t.x = f2tf32(v.x); t.y = f2tf32(v.y); t.z = f2tf32(v.z); t.w = f2tf32(v.w);
        *reinterpret_cast<float4*>(&Qs[r * QPAD + lc]) = t;
    }

    float m_st[2][2] = {{-1e30f, -1e30f}, {-1e30f, -1e30f}};
    float l_st[2][2] = {{0.f, 0.f}, {0.f, 0.f}};
    float o[2][8][4];
#pragma unroll
    for (int rbk = 0; rbk < 2; rbk++)
#pragma unroll
        for (int dt = 0; dt < 8; dt++)
#pragma unroll
            for (int r = 0; r < 4; r++) o[rbk][dt][r] = 0.f;

    const int rowbase = warp * 32;
    const float* biasb = bias + (size_t)b * SKVLEN;

    for (int kv0 = 0; kv0 < SKVLEN; kv0 += KVT) {
        // Load K,V 32x64 tiles (TF32-rounded)
        const float* Kg = g_k + (size_t)(b * SKVLEN + kv0) * EMBED + h * HDIM;
        const float* Vg = g_v + (size_t)(b * SKVLEN + kv0) * EMBED + h * HDIM;
        __syncthreads();   // previous iter's consumers done before overwrite
#pragma unroll
        for (int p = 0; p < 4; p++) {
            int r = lr + p * 8;
            float4 kv4 = *reinterpret_cast<const float4*>(&Kg[(size_t)r * EMBED + lc]);
            float4 tk;
            tk.x = f2tf32(kv4.x); tk.y = f2tf32(kv4.y);
            tk.z = f2tf32(kv4.z); tk.w = f2tf32(kv4.w);
            *reinterpret_cast<float4*>(&Ks[r * KPAD + lc]) = tk;
            float4 vv4 = *reinterpret_cast<const float4*>(&Vg[(size_t)r * EMBED + lc]);
            float4 tv;
            tv.x = f2tf32(vv4.x); tv.y = f2tf32(vv4.y);
            tv.z = f2tf32(vv4.z); tv.w = f2tf32(vv4.w);
            *reinterpret_cast<float4*>(&Vs[r * VPAD + lc]) = tv;
        }
        __syncthreads();

        // ---- S = Q @ K^T (32 q rows x 32 kv cols per warp) ----
        float s[2][4][4];
#pragma unroll
        for (int rbk = 0; rbk < 2; rbk++)
#pragma unroll
            for (int nt = 0; nt < 4; nt++)
#pragma unroll
                for (int r = 0; r < 4; r++) s[rbk][nt][r] = 0.f;

#pragma unroll
        for (int ks = 0; ks < 8; ks++) {
            uint32_t af[2][4];
#pragma unroll
            for (int rbk = 0; rbk < 2; rbk++) {
                int r0 = rowbase + rbk * 16;
                af[rbk][0] = __float_as_uint(Qs[(r0 + g) * QPAD + ks * 8 + tg]);
                af[rbk][1] = __float_as_uint(Qs[(r0 + g + 8) * QPAD + ks * 8 + tg]);
                af[rbk][2] = __float_as_uint(Qs[(r0 + g) * QPAD + ks * 8 + tg + 4]);
                af[rbk][3] = __float_as_uint(Qs[(r0 + g + 8) * QPAD + ks * 8 + tg + 4]);
            }
#pragma unroll
            for (int nt = 0; nt < 4; nt++) {
                uint32_t b0 = __float_as_uint(Ks[(nt * 8 + g) * KPAD + ks * 8 + tg]);
                uint32_t b1 = __float_as_uint(Ks[(nt * 8 + g) * KPAD + ks * 8 + tg + 4]);
                mma_tf32(s[0][nt], af[0][0], af[0][1], af[0][2], af[0][3], b0, b1);
                mma_tf32(s[1][nt], af[1][0], af[1][1], af[1][2], af[1][3], b0, b1);
            }
        }

        // ---- scale + bias + online softmax ----
        float mnew[2][2] = {{m_st[0][0], m_st[0][1]}, {m_st[1][0], m_st[1][1]}};
#pragma unroll
        for (int nt = 0; nt < 4; nt++) {
            int c = kv0 + nt * 8 + 2 * tg;
            float b0v = __ldg(&biasb[c]);
            float b1v = __ldg(&biasb[c + 1]);
#pragma unroll
            for (int rbk = 0; rbk < 2; rbk++) {
                s[rbk][nt][0] = s[rbk][nt][0] * 0.125f + b0v;
                s[rbk][nt][1] = s[rbk][nt][1] * 0.125f + b1v;
                s[rbk][nt][2] = s[rbk][nt][2] * 0.125f + b0v;
                s[rbk][nt][3] = s[rbk][nt][3] * 0.125f + b1v;
                mnew[rbk][0] = fmaxf(mnew[rbk][0], fmaxf(s[rbk][nt][0], s[rbk][nt][1]));
                mnew[rbk][1] = fmaxf(mnew[rbk][1], fmaxf(s[rbk][nt][2], s[rbk][nt][3]));
            }
        }
#pragma unroll
        for (int rbk = 0; rbk < 2; rbk++)
#pragma unroll
            for (int hh = 0; hh < 2; hh++) {
                mnew[rbk][hh] = fmaxf(mnew[rbk][hh], __shfl_xor_sync(0xffffffffu, mnew[rbk][hh], 1));
                mnew[rbk][hh] = fmaxf(mnew[rbk][hh], __shfl_xor_sync(0xffffffffu, mnew[rbk][hh], 2));
            }

        float alpha[2][2];
        float rowsum[2][2] = {{0.f, 0.f}, {0.f, 0.f}};
#pragma unroll
        for (int rbk = 0; rbk < 2; rbk++) {
            alpha[rbk][0] = __expf(m_st[rbk][0] - mnew[rbk][0]);
            alpha[rbk][1] = __expf(m_st[rbk][1] - mnew[rbk][1]);
#pragma unroll
            for (int nt = 0; nt < 4; nt++) {
                s[rbk][nt][0] = __expf(s[rbk][nt][0] - mnew[rbk][0]);
                s[rbk][nt][1] = __expf(s[rbk][nt][1] - mnew[rbk][0]);
                s[rbk][nt][2] = __expf(s[rbk][nt][2] - mnew[rbk][1]);
                s[rbk][nt][3] = __expf(s[rbk][nt][3] - mnew[rbk][1]);
                rowsum[rbk][0] += s[rbk][nt][0] + s[rbk][nt][1];
                rowsum[rbk][1] += s[rbk][nt][2] + s[rbk][nt][3];
            }
        }
#pragma unroll
        for (int rbk = 0; rbk < 2; rbk++)
#pragma unroll
            for (int hh = 0; hh < 2; hh++) {
                rowsum[rbk][hh] += __shfl_xor_sync(0xffffffffu, rowsum[rbk][hh], 1);
                rowsum[rbk][hh] += __shfl_xor_sync(0xffffffffu, rowsum[rbk][hh], 2);
                l_st[rbk][hh] = l_st[rbk][hh] * alpha[rbk][hh] + rowsum[rbk][hh];
                m_st[rbk][hh] = mnew[rbk][hh];
            }

        // rescale running O
#pragma unroll
        for (int rbk = 0; rbk < 2; rbk++)
#pragma unroll
            for (int dt = 0; dt < 8; dt++) {
                o[rbk][dt][0] *= alpha[rbk][0];
                o[rbk][dt][1] *= alpha[rbk][0];
                o[rbk][dt][2] *= alpha[rbk][1];
                o[rbk][dt][3] *= alpha[rbk][1];
            }

        // ---- O += P @ V, with shuffle-based S->A fragment conversion ----
        const int base   = lane & ~3;
        const int src_lo = base + (tg >> 1);
        const int src_hi = base + 2 + (tg >> 1);
        const bool odd   = (tg & 1);
#pragma unroll
        for (int ks = 0; ks < 4; ks++) {
            uint32_t af[2][4];
#pragma unroll
            for (int rbk = 0; rbk < 2; rbk++) {
                float s0 = s[rbk][ks][0], s1 = s[rbk][ks][1];
                float s2 = s[rbk][ks][2], s3 = s[rbk][ks][3];
                float u0 = __shfl_sync(0xffffffffu, s0, src_lo);
                float u1 = __shfl_sync(0xffffffffu, s1, src_lo);
                float v0 = __shfl_sync(0xffffffffu, s0, src_hi);
                float v1 = __shfl_sync(0xffffffffu, s1, src_hi);
                float w0 = __shfl_sync(0xffffffffu, s2, src_lo);
                float w1 = __shfl_sync(0xffffffffu, s3, src_lo);
                float x0 = __shfl_sync(0xffffffffu, s2, src_hi);
                float x1 = __shfl_sync(0xffffffffu, s3, src_hi);
                float aT  = odd ? u1 : u0;   // (row g,    col tg)
                float aT4 = odd ? v1 : v0;   // (row g,    col tg+4)
                float aB  = odd ? w1 : w0;   // (row g+8,  col tg)
                float aB4 = odd ? x1 : x0;   // (row g+8,  col tg+4)
                af[rbk][0] = __float_as_uint(f2tf32(aT));
                af[rbk][1] = __float_as_uint(f2tf32(aB));
                af[rbk][2] = __float_as_uint(f2tf32(aT4));
                af[rbk][3] = __float_as_uint(f2tf32(aB4));
            }
#pragma unroll
            for (int dt = 0; dt < 8; dt++) {
                uint32_t b0 = __float_as_uint(Vs[(ks * 8 + tg) * VPAD + dt * 8 + g]);
                uint32_t b1 = __float_as_uint(Vs[(ks * 8 + tg + 4) * VPAD + dt * 8 + g]);
                mma_tf32(o[0][dt], af[0][0], af[0][1], af[0][2], af[0][3], b0, b1);
                mma_tf32(o[1][dt], af[1][0], af[1][1], af[1][2], af[1][3], b0, b1);
            }
        }
    }

    // Epilogue: O / l
    float* Og = g_attn + (size_t)(b * SQLEN) * EMBED + h * HDIM;
#pragma unroll
    for (int rbk = 0; rbk < 2; rbk++) {
        float inv0 = 1.f / l_st[rbk][0];
        float inv1 = 1.f / l_st[rbk][1];
        int q0 = qt * 128 + rowbase + rbk * 16 + g;
#pragma unroll
        for (int dt = 0; dt < 8; dt++) {
            int c = dt * 8 + 2 * tg;
            float2 lo = {o[rbk][dt][0] * inv0, o[rbk][dt][1] * inv0};
            float2 hi = {o[rbk][dt][2] * inv1, o[rbk][dt][3] * inv1};
            *reinterpret_cast<float2*>(&Og[(size_t)q0 * EMBED + c])       = lo;
            *reinterpret_cast<float2*>(&Og[(size_t)(q0 + 8) * EMBED + c]) = hi;
        }
    }
}

// ---------------------------------------------------------------------------
// Launch
// ---------------------------------------------------------------------------
extern "C" void kernel_launch(void* const* d_in, const int* in_sizes, int n_in,
                              void* d_out, int out_size) {
    const float* query = (const float*)d_in[0];
    const float* key   = (const float*)d_in[1];
    const float* value = (const float*)d_in[2];
    const float* bias  = (const float*)d_in[3];
    const float* Wq    = (const float*)d_in[4];
    const float* Wk    = (const float*)d_in[5];
    const float* Wv    = (const float*)d_in[6];
    const float* Wo    = (const float*)d_in[7];
    float* out = (float*)d_out;

    float *gq, *gk, *gv, *ga;
    cudaGetSymbolAddress((void**)&gq, g_q);
    cudaGetSymbolAddress((void**)&gk, g_k);
    cudaGetSymbolAddress((void**)&gv, g_v);
    cudaGetSymbolAddress((void**)&ga, g_attn);

    cudaFuncSetAttribute(attn_kernel, cudaFuncAttributeMaxDynamicSharedMemorySize,
                         ATTN_SMEM);

    dim3 qkv_grid(EMBED / GBN, MTOT / GBM, 3);   // (8, 32, 3)
    gemm_qkv<<<qkv_grid, 256>>>(query, key, value, Wq, Wk, Wv, gq, gk, gv);

    dim3 attn_grid(SQLEN / 128, NHEAD, BATCH);   // (16, 16, 2)
    attn_kernel<<<attn_grid, 128, ATTN_SMEM>>>(bias);

    dim3 o_grid(EMBED / GBN, MTOT / GBM);        // (8, 32)
    gemm_single<<<o_grid, 256>>>(ga, Wo, out);
}